// round 16
// baseline (speedup 1.0000x reference)
#include <cuda_runtime.h>
#include <cstdint>

#define NN 100000
#define EE 1600000
#define HID 64

// ---------------- device scratch (no runtime allocation allowed) ------------
__device__ float g_B0[NN * HID];
__device__ float g_B1[NN * HID];
__device__ float g_B2[NN * HID];
__device__ float g_dinv[NN];
__device__ float g_deg[NN];
__device__ float g_z2[(size_t)EE * (HID / 2)];
__device__ double g_s1[HID], g_q1[HID];
__device__ double g_s2[HID / 2], g_q2[HID / 2];
__device__ float g_W2f[HID * (HID / 2)];
__device__ float g_b2f[HID / 2];
__device__ float g_W3f[(HID / 2) * 2];
__device__ float g_b3f[2];

// ---------------- degree + stats init ---------------------------------------
__global__ void deg_init_kernel(int n) {
    int v = blockIdx.x * 256 + threadIdx.x;
    if (v < n) g_deg[v] = 1.0f;  // self-loop
    if (blockIdx.x == 0) {
        int t = threadIdx.x;
        if (t < HID) { g_s1[t] = 0.0; g_q1[t] = 0.0; }
        if (t < HID / 2) { g_s2[t] = 0.0; g_q2[t] = 0.0; }
    }
}

__global__ void deg_count_kernel(const int* __restrict__ ei, int E) {
    int e = blockIdx.x * 256 + threadIdx.x;
    if (e < E) atomicAdd(&g_deg[ei[(size_t)E + e]], 1.0f);
}

// ---------------- layer-1 GEMM (K=3) + fused self-init + fused dinv ---------
__global__ __launch_bounds__(256) void gemm_k3_kernel(
    const float* __restrict__ X, const float* __restrict__ W,
    const float* __restrict__ bias,
    float* __restrict__ C, float* __restrict__ O, int n)
{
    __shared__ float Ws[3 * 64];
    int tid = threadIdx.x;
    if (tid < 192) Ws[tid] = W[tid];
    __syncthreads();
    int idx = blockIdx.x * 256 + tid;
    int v = idx >> 4;
    int c4 = (idx & 15) * 4;
    if (v >= n) return;
    float dv = rsqrtf(g_deg[v]);
    if ((idx & 15) == 0) g_dinv[v] = dv;   // consumed by later scatters
    float x0 = X[v * 3 + 0], x1 = X[v * 3 + 1], x2 = X[v * 3 + 2];
    float4 w0 = *(const float4*)&Ws[0 * 64 + c4];
    float4 w1 = *(const float4*)&Ws[1 * 64 + c4];
    float4 w2 = *(const float4*)&Ws[2 * 64 + c4];
    float4 o;
    o.x = x0 * w0.x + x1 * w1.x + x2 * w2.x;
    o.y = x0 * w0.y + x1 * w1.y + x2 * w2.y;
    o.z = x0 * w0.z + x1 * w1.z + x2 * w2.z;
    o.w = x0 * w0.w + x1 * w1.w + x2 * w2.w;
    *(float4*)&C[v * 64 + c4] = o;
    float sw = dv * dv;
    float4 b4 = *(const float4*)&bias[c4];
    float4 s;
    s.x = b4.x + o.x * sw; s.y = b4.y + o.y * sw;
    s.z = b4.z + o.z * sw; s.w = b4.w + o.w * sw;
    *(float4*)&O[(size_t)v * 64 + c4] = s;
}

// ---------------- 64x64 tiled GEMM + optional fused self-init ---------------
__global__ __launch_bounds__(256) void gemm64_kernel(
    const float* __restrict__ A, const float* __restrict__ W,
    float* __restrict__ C, const float* __restrict__ bias_self,
    float* __restrict__ O, int n, int relu_in)
{
    __shared__ float As[64 * 68];
    __shared__ float Ws[64 * 64];
    int tid = threadIdx.x;
    int rowbase = blockIdx.x * 64;

    for (int i = tid; i < 1024; i += 256)
        ((float4*)Ws)[i] = ((const float4*)W)[i];

    for (int i = tid; i < 1024; i += 256) {
        int r = i >> 4;
        int c4 = (i & 15) * 4;
        float4 v;
        if (rowbase + r < n) v = *(const float4*)&A[(size_t)(rowbase + r) * 64 + c4];
        else v = make_float4(0.f, 0.f, 0.f, 0.f);
        if (relu_in) {
            v.x = fmaxf(v.x, 0.f); v.y = fmaxf(v.y, 0.f);
            v.z = fmaxf(v.z, 0.f); v.w = fmaxf(v.w, 0.f);
        }
        *(float4*)&As[r * 68 + c4] = v;
    }
    __syncthreads();

    int rg = (tid >> 4) * 4;
    int cg = (tid & 15) * 4;
    float4 acc0 = make_float4(0, 0, 0, 0), acc1 = acc0, acc2 = acc0, acc3 = acc0;
#pragma unroll
    for (int k = 0; k < 64; k++) {
        float4 wv = *(const float4*)&Ws[k * 64 + cg];
        float a0 = As[(rg + 0) * 68 + k];
        float a1 = As[(rg + 1) * 68 + k];
        float a2 = As[(rg + 2) * 68 + k];
        float a3 = As[(rg + 3) * 68 + k];
        acc0.x += a0 * wv.x; acc0.y += a0 * wv.y; acc0.z += a0 * wv.z; acc0.w += a0 * wv.w;
        acc1.x += a1 * wv.x; acc1.y += a1 * wv.y; acc1.z += a1 * wv.z; acc1.w += a1 * wv.w;
        acc2.x += a2 * wv.x; acc2.y += a2 * wv.y; acc2.z += a2 * wv.z; acc2.w += a2 * wv.w;
        acc3.x += a3 * wv.x; acc3.y += a3 * wv.y; acc3.z += a3 * wv.z; acc3.w += a3 * wv.w;
    }
    float4 accs[4] = {acc0, acc1, acc2, acc3};
#pragma unroll
    for (int rr = 0; rr < 4; rr++) {
        int row = rowbase + rg + rr;
        if (row < n) {
            *(float4*)&C[(size_t)row * 64 + cg] = accs[rr];
            if (O) {
                float dv = g_dinv[row];
                float sw = dv * dv;
                float4 b4 = *(const float4*)&bias_self[cg];
                float4 s;
                s.x = b4.x + accs[rr].x * sw; s.y = b4.y + accs[rr].y * sw;
                s.z = b4.z + accs[rr].z * sw; s.w = b4.w + accs[rr].w * sw;
                *(float4*)&O[(size_t)row * 64 + cg] = s;
            }
        }
    }
}

// ------- dual 64x64 GEMM: Ca = A@W[0:64], Cb = A@W[64:128] (one A pass) -----
__global__ __launch_bounds__(256) void gemm64_dual_kernel(
    const float* __restrict__ A, const float* __restrict__ W,  // W: [128,64]
    float* __restrict__ Ca, float* __restrict__ Cb, int n)
{
    __shared__ float As[64 * 68];
    __shared__ float Ws[128 * 64];
    int tid = threadIdx.x;
    int rowbase = blockIdx.x * 64;

    for (int i = tid; i < 2048; i += 256)
        ((float4*)Ws)[i] = ((const float4*)W)[i];

    for (int i = tid; i < 1024; i += 256) {
        int r = i >> 4;
        int c4 = (i & 15) * 4;
        float4 v;
        if (rowbase + r < n) v = *(const float4*)&A[(size_t)(rowbase + r) * 64 + c4];
        else v = make_float4(0.f, 0.f, 0.f, 0.f);
        *(float4*)&As[r * 68 + c4] = v;
    }
    __syncthreads();

    int rg = (tid >> 4) * 4;
    int cg = (tid & 15) * 4;
    float4 a0c = make_float4(0, 0, 0, 0), a1c = a0c, a2c = a0c, a3c = a0c;
    float4 b0c = a0c, b1c = a0c, b2c = a0c, b3c = a0c;
#pragma unroll
    for (int k = 0; k < 64; k++) {
        float4 wa = *(const float4*)&Ws[k * 64 + cg];
        float4 wb = *(const float4*)&Ws[(64 + k) * 64 + cg];
        float a0 = As[(rg + 0) * 68 + k];
        float a1 = As[(rg + 1) * 68 + k];
        float a2 = As[(rg + 2) * 68 + k];
        float a3 = As[(rg + 3) * 68 + k];
        a0c.x += a0 * wa.x; a0c.y += a0 * wa.y; a0c.z += a0 * wa.z; a0c.w += a0 * wa.w;
        a1c.x += a1 * wa.x; a1c.y += a1 * wa.y; a1c.z += a1 * wa.z; a1c.w += a1 * wa.w;
        a2c.x += a2 * wa.x; a2c.y += a2 * wa.y; a2c.z += a2 * wa.z; a2c.w += a2 * wa.w;
        a3c.x += a3 * wa.x; a3c.y += a3 * wa.y; a3c.z += a3 * wa.z; a3c.w += a3 * wa.w;
        b0c.x += a0 * wb.x; b0c.y += a0 * wb.y; b0c.z += a0 * wb.z; b0c.w += a0 * wb.w;
        b1c.x += a1 * wb.x; b1c.y += a1 * wb.y; b1c.z += a1 * wb.z; b1c.w += a1 * wb.w;
        b2c.x += a2 * wb.x; b2c.y += a2 * wb.y; b2c.z += a2 * wb.z; b2c.w += a2 * wb.w;
        b3c.x += a3 * wb.x; b3c.y += a3 * wb.y; b3c.z += a3 * wb.z; b3c.w += a3 * wb.w;
    }
    float4 aacc[4] = {a0c, a1c, a2c, a3c};
    float4 bacc[4] = {b0c, b1c, b2c, b3c};
#pragma unroll
    for (int rr = 0; rr < 4; rr++) {
        int row = rowbase + rg + rr;
        if (row < n) {
            *(float4*)&Ca[(size_t)row * 64 + cg] = aacc[rr];
            *(float4*)&Cb[(size_t)row * 64 + cg] = bacc[rr];
        }
    }
}

// ---------------- edge scatter: O[col] += T[row] * dinv[row]*dinv[col] -------
__global__ __launch_bounds__(256) void scatter_kernel(
    const int* __restrict__ ei, const float* __restrict__ T,
    float* __restrict__ O, int E)
{
    long long idx = (long long)blockIdx.x * 256 + threadIdx.x;
    int e = (int)(idx >> 4);
    int part = ((int)idx & 15) * 4;
    if (e >= E) return;
    int r = ei[e];
    int c = ei[(size_t)E + e];
    float w = g_dinv[r] * g_dinv[c];
    float4 v = *(const float4*)&T[(size_t)r * 64 + part];
    v.x *= w; v.y *= w; v.z *= w; v.w *= w;
    float* p = &O[(size_t)c * 64 + part];
    asm volatile("red.global.add.v4.f32 [%0], {%1,%2,%3,%4};"
                 :: "l"(p), "f"(v.x), "f"(v.y), "f"(v.z), "f"(v.w) : "memory");
}

// ---------------- edge pass 1: BN1 statistics of z1 -------------------------
__global__ __launch_bounds__(256) void edge_pass1_kernel(
    const int* __restrict__ ei, const float* __restrict__ A,
    const float* __restrict__ B, const float* __restrict__ bm1, int E)
{
    int lane = threadIdx.x & 31;
    int wid = threadIdx.x >> 5;
    int gw = blockIdx.x * 8 + wid;
    int nw = gridDim.x * 8;
    float ba = bm1[lane], bb = bm1[lane + 32];
    float s0 = 0.f, q0 = 0.f, s1 = 0.f, q1 = 0.f;
    for (int e = gw; e < E; e += nw) {
        int s = ei[e];
        int d = ei[(size_t)E + e];
        float z = A[(size_t)s * 64 + lane] + B[(size_t)d * 64 + lane] + ba;
        z = fmaxf(z, 0.f);
        float w = A[(size_t)s * 64 + lane + 32] + B[(size_t)d * 64 + lane + 32] + bb;
        w = fmaxf(w, 0.f);
        s0 += z; q0 += z * z;
        s1 += w; q1 += w * w;
    }
    __shared__ float sh[8][64];
    sh[wid][lane] = s0; sh[wid][lane + 32] = s1;
    __syncthreads();
    if (threadIdx.x < 64) {
        float t = 0.f;
        for (int w = 0; w < 8; w++) t += sh[w][threadIdx.x];
        atomicAdd(&g_s1[threadIdx.x], (double)t);
    }
    __syncthreads();
    sh[wid][lane] = q0; sh[wid][lane + 32] = q1;
    __syncthreads();
    if (threadIdx.x < 64) {
        float t = 0.f;
        for (int w = 0; w < 8; w++) t += sh[w][threadIdx.x];
        atomicAdd(&g_q1[threadIdx.x], (double)t);
    }
}

// ---------------- fold BN1 into Wm2 -----------------------------------------
__global__ void fold1_kernel(const float* __restrict__ Wm2,
                             const float* __restrict__ bm2,
                             const float* __restrict__ g1,
                             const float* __restrict__ be1, double inv)
{
    int m = threadIdx.x;  // 32
    float bacc = bm2[m];
    for (int j = 0; j < 64; j++) {
        double mu = g_s1[j] * inv;
        double var = g_q1[j] * inv - mu * mu;
        float s = g1[j] * rsqrtf((float)var + 1e-5f);
        float t = be1[j] - (float)mu * s;
        float w = Wm2[j * 32 + m];
        g_W2f[j * 32 + m] = s * w;
        bacc += t * w;
    }
    g_b2f[m] = bacc;
}

// ---- edge pass 2 (pipelined tiles): z2 = relu(z1@W2f + b2f); fused BN2 stats
// Register-prefetch pipeline: gather tile t+1 (LDG in flight) while the FFMA
// GEMM consumes tile t from smem. Edge indices via warp-broadcast LDG.
__global__ __launch_bounds__(256) void edge_pass2_kernel(
    const int* __restrict__ ei, const float* __restrict__ A,
    const float* __restrict__ B, const float* __restrict__ bm1, int E)
{
    __shared__ float Zs[64][68];
    __shared__ float Ws[64 * 32];
    __shared__ float bs[64];
    __shared__ float b2s[32];
    __shared__ float blk_s[32], blk_q[32];

    int tid = threadIdx.x;
    int lane = tid & 31;
    int wid = tid >> 5;
    if (tid < 64) bs[tid] = bm1[tid];
    if (tid < 32) { b2s[tid] = g_b2f[tid]; blk_s[tid] = 0.f; blk_q[tid] = 0.f; }
    for (int i = tid; i < 2048; i += 256) Ws[i] = g_W2f[i];
    __syncthreads();

    int r0 = (tid >> 3) * 2;        // rows r0, r0+1
    int cg = (tid & 7) * 4;         // cols cg..cg+3
    int rbase = wid * 8;            // staging rows for this warp

    float st_s[4] = {0.f, 0.f, 0.f, 0.f};
    float st_q[4] = {0.f, 0.f, 0.f, 0.f};

    int ntiles = (E + 63) >> 6;

    float2 va[8], vb[8];
    int tile = blockIdx.x;

    // prologue: gather tile 0
    if (tile < ntiles) {
#pragma unroll
        for (int rr = 0; rr < 8; rr++) {
            int e = tile * 64 + rbase + rr;
            if (e < E) {
                int s = ei[e];                       // warp-broadcast
                int d = ei[(size_t)E + e];
                va[rr] = ((const float2*)&A[(size_t)s * 64])[lane];
                vb[rr] = ((const float2*)&B[(size_t)d * 64])[lane];
            } else {
                va[rr] = make_float2(0.f, 0.f);
                vb[rr] = make_float2(0.f, 0.f);
            }
        }
    }

    while (tile < ntiles) {
        int e0 = tile << 6;
        // store staged regs -> Zs (bias + relu applied here)
#pragma unroll
        for (int rr = 0; rr < 8; rr++) {
            bool valid = (e0 + rbase + rr) < E;
            float z0 = valid ? fmaxf(va[rr].x + vb[rr].x + bs[2 * lane], 0.f) : 0.f;
            float z1 = valid ? fmaxf(va[rr].y + vb[rr].y + bs[2 * lane + 1], 0.f) : 0.f;
            Zs[rbase + rr][2 * lane] = z0;
            Zs[rbase + rr][2 * lane + 1] = z1;
        }
        int ntile = tile + gridDim.x;
        __syncthreads();   // Zs ready for everyone

        // issue next tile's gathers NOW — LDGs overlap the GEMM below
        if (ntile < ntiles) {
#pragma unroll
            for (int rr = 0; rr < 8; rr++) {
                int e = ntile * 64 + rbase + rr;
                if (e < E) {
                    int s = ei[e];
                    int d = ei[(size_t)E + e];
                    va[rr] = ((const float2*)&A[(size_t)s * 64])[lane];
                    vb[rr] = ((const float2*)&B[(size_t)d * 64])[lane];
                } else {
                    va[rr] = make_float2(0.f, 0.f);
                    vb[rr] = make_float2(0.f, 0.f);
                }
            }
        }

        // GEMM: 2 rows x 4 cols per thread over k=64
        float acc0[4], acc1[4];
#pragma unroll
        for (int j = 0; j < 4; j++) { acc0[j] = b2s[cg + j]; acc1[j] = b2s[cg + j]; }
#pragma unroll
        for (int k = 0; k < 64; k += 4) {
            float a0r[4], a1r[4];
            *(float4*)a0r = *(const float4*)&Zs[r0][k];
            *(float4*)a1r = *(const float4*)&Zs[r0 + 1][k];
#pragma unroll
            for (int kk = 0; kk < 4; kk++) {
                float wr[4];
                *(float4*)wr = *(const float4*)&Ws[(k + kk) * 32 + cg];
#pragma unroll
                for (int j = 0; j < 4; j++) {
                    acc0[j] += a0r[kk] * wr[j];
                    acc1[j] += a1r[kk] * wr[j];
                }
            }
        }

        float o0[4], o1[4];
#pragma unroll
        for (int j = 0; j < 4; j++) {
            o0[j] = fmaxf(acc0[j], 0.f);
            o1[j] = fmaxf(acc1[j], 0.f);
        }
        if (e0 + r0 < E) {
            *(float4*)&g_z2[(size_t)(e0 + r0) * 32 + cg] = *(float4*)o0;
#pragma unroll
            for (int j = 0; j < 4; j++) { st_s[j] += o0[j]; st_q[j] += o0[j] * o0[j]; }
        }
        if (e0 + r0 + 1 < E) {
            *(float4*)&g_z2[(size_t)(e0 + r0 + 1) * 32 + cg] = *(float4*)o1;
#pragma unroll
            for (int j = 0; j < 4; j++) { st_s[j] += o1[j]; st_q[j] += o1[j] * o1[j]; }
        }
        __syncthreads();   // GEMM reads done; Zs reusable next iter
        tile = ntile;
    }

    // flush per-block stats
#pragma unroll
    for (int j = 0; j < 4; j++) {
        atomicAdd(&blk_s[cg + j], st_s[j]);
        atomicAdd(&blk_q[cg + j], st_q[j]);
    }
    __syncthreads();
    if (tid < 32) {
        atomicAdd(&g_s2[tid], (double)blk_s[tid]);
        atomicAdd(&g_q2[tid], (double)blk_q[tid]);
    }
}

// ---------------- fold BN2 into Wm3 -----------------------------------------
__global__ void fold2_kernel(const float* __restrict__ Wm3,
                             const float* __restrict__ bm3,
                             const float* __restrict__ g2,
                             const float* __restrict__ be2, double inv)
{
    int k = threadIdx.x;
    if (k >= 2) return;
    float bacc = bm3[k];
    for (int m = 0; m < 32; m++) {
        double mu = g_s2[m] * inv;
        double var = g_q2[m] * inv - mu * mu;
        float s = g2[m] * rsqrtf((float)var + 1e-5f);
        float t = be2[m] - (float)mu * s;
        float w = Wm3[m * 2 + k];
        g_W3f[m * 2 + k] = s * w;
        bacc += t * w;
    }
    g_b3f[k] = bacc;
}

// ---------------- edge pass 3: out = z2 @ W3f + b3f -------------------------
__global__ __launch_bounds__(256) void edge_pass3_kernel(float* __restrict__ out, int E) {
    __shared__ float W0[32], W1s[32];
    __shared__ float bb[2];
    int tid = threadIdx.x;
    if (tid < 32) { W0[tid] = g_W3f[tid * 2]; W1s[tid] = g_W3f[tid * 2 + 1]; }
    if (tid < 2) bb[tid] = g_b3f[tid];
    __syncthreads();
    int stride = gridDim.x * 256;
    for (int e = blockIdx.x * 256 + tid; e < E; e += stride) {
        const float4* z4 = (const float4*)&g_z2[(size_t)e * 32];
        float o0 = bb[0], o1 = bb[1];
#pragma unroll
        for (int m4 = 0; m4 < 8; m4++) {
            float4 z = z4[m4];
            o0 += z.x * W0[m4 * 4 + 0] + z.y * W0[m4 * 4 + 1] +
                  z.z * W0[m4 * 4 + 2] + z.w * W0[m4 * 4 + 3];
            o1 += z.x * W1s[m4 * 4 + 0] + z.y * W1s[m4 * 4 + 1] +
                  z.z * W1s[m4 * 4 + 2] + z.w * W1s[m4 * 4 + 3];
        }
        *(float2*)&out[(size_t)e * 2] = make_float2(o0, o1);
    }
}

// ---------------- host launcher ---------------------------------------------
extern "C" void kernel_launch(void* const* d_in, const int* in_sizes, int n_in,
                              void* d_out, int out_size)
{
    const float* x = (const float*)d_in[0];
    const int* ei = (const int*)d_in[1];
    const float* W1 = (const float*)d_in[2];
    const float* b1 = (const float*)d_in[3];
    const float* W2 = (const float*)d_in[4];
    const float* b2 = (const float*)d_in[5];
    const float* W3 = (const float*)d_in[6];
    const float* b3 = (const float*)d_in[7];
    const float* Wm1 = (const float*)d_in[8];
    const float* bm1 = (const float*)d_in[9];
    const float* g1 = (const float*)d_in[10];
    const float* be1 = (const float*)d_in[11];
    const float* Wm2 = (const float*)d_in[12];
    const float* bm2 = (const float*)d_in[13];
    const float* g2 = (const float*)d_in[14];
    const float* be2 = (const float*)d_in[15];
    const float* Wm3 = (const float*)d_in[16];
    const float* bm3 = (const float*)d_in[17];

    int n = in_sizes[0] / 3;
    int E = in_sizes[1] / 2;

    float *B0, *B1p, *B2;
    cudaGetSymbolAddress((void**)&B0, g_B0);
    cudaGetSymbolAddress((void**)&B1p, g_B1);
    cudaGetSymbolAddress((void**)&B2, g_B2);

    int nb_node = (n + 255) / 256;
    int nb_edge = (E + 255) / 256;
    int nb_node16 = (n * 16 + 255) / 256;
    int nb_edge16 = (int)(((long long)E * 16 + 255) / 256);
    int nb_gemm = (n + 63) / 64;

    // degree (+ stats zero fused); dinv computed inside gemm_k3
    deg_init_kernel<<<nb_node, 256>>>(n);
    deg_count_kernel<<<nb_edge, 256>>>(ei, E);

    // layer 1: B0 = x@W1 ; dinv ; B1 = b1 + B0*dinv^2 ; scatter into B1
    gemm_k3_kernel<<<nb_node16, 256>>>(x, W1, b1, B0, B1p, n);
    scatter_kernel<<<nb_edge16, 256>>>(ei, B0, B1p, E);

    // layer 2: B0 = relu(B1)@W2 ; B2 = b2 + B0*dinv^2 (fused) ; scatter into B2
    gemm64_kernel<<<nb_gemm, 256>>>(B1p, W2, B0, b2, B2, n, 1);
    scatter_kernel<<<nb_edge16, 256>>>(ei, B0, B2, E);

    // layer 3: B0 = relu(B2)@W3 ; B1 = b3 + B0*dinv^2 (fused) ; scatter into B1 (= h3)
    gemm64_kernel<<<nb_gemm, 256>>>(B2, W3, B0, b3, B1p, n, 1);
    scatter_kernel<<<nb_edge16, 256>>>(ei, B0, B1p, E);

    // projections (single pass over h3): a -> B0 ; b -> B2
    gemm64_dual_kernel<<<nb_gemm, 256>>>(B1p, Wm1, B0, B2, n);

    // edge MLP (stats2 fused into pass2)
    edge_pass1_kernel<<<1024, 256>>>(ei, B0, B2, bm1, E);
    fold1_kernel<<<1, 32>>>(Wm2, bm2, g1, be1, 1.0 / (double)E);
    edge_pass2_kernel<<<2048, 256>>>(ei, B0, B2, bm1, E);
    fold2_kernel<<<1, 32>>>(Wm3, bm3, g2, be2, 1.0 / (double)E);
    edge_pass3_kernel<<<2048, 256>>>((float*)d_out, E);
}

// round 17
// speedup vs baseline: 1.4723x; 1.4723x over previous
#include <cuda_runtime.h>
#include <cstdint>

#define NN 100000
#define EE 1600000
#define HID 64

// ---------------- device scratch (no runtime allocation allowed) ------------
__device__ float g_B0[NN * HID];
__device__ float g_B1[NN * HID];
__device__ float g_B2[NN * HID];
__device__ float g_dinv[NN];
__device__ float g_deg[NN];
__device__ float g_z2[(size_t)EE * (HID / 2)];
__device__ double g_s1[HID], g_q1[HID];
__device__ double g_s2[HID / 2], g_q2[HID / 2];
__device__ float g_W2f[HID * (HID / 2)];
__device__ float g_b2f[HID / 2];
__device__ float g_W3f[(HID / 2) * 2];
__device__ float g_b3f[2];

// ---------------- degree + stats init ---------------------------------------
__global__ void deg_init_kernel(int n) {
    int v = blockIdx.x * 256 + threadIdx.x;
    if (v < n) g_deg[v] = 1.0f;  // self-loop
    if (blockIdx.x == 0) {
        int t = threadIdx.x;
        if (t < HID) { g_s1[t] = 0.0; g_q1[t] = 0.0; }
        if (t < HID / 2) { g_s2[t] = 0.0; g_q2[t] = 0.0; }
    }
}

__global__ void deg_count_kernel(const int* __restrict__ ei, int E) {
    int e = blockIdx.x * 256 + threadIdx.x;
    if (e < E) atomicAdd(&g_deg[ei[(size_t)E + e]], 1.0f);
}

__global__ void deg_finish_kernel(int n) {
    int v = blockIdx.x * 256 + threadIdx.x;
    if (v < n) g_dinv[v] = rsqrtf(g_deg[v]);
}

// ---------------- layer-1 GEMM (K=3) + fused self-init ----------------------
__global__ __launch_bounds__(256) void gemm_k3_kernel(
    const float* __restrict__ X, const float* __restrict__ W,
    const float* __restrict__ bias,
    float* __restrict__ C, float* __restrict__ O, int n)
{
    __shared__ float Ws[3 * 64];
    int tid = threadIdx.x;
    if (tid < 192) Ws[tid] = W[tid];
    __syncthreads();
    int idx = blockIdx.x * 256 + tid;
    int v = idx >> 4;
    int c4 = (idx & 15) * 4;
    if (v >= n) return;
    float x0 = X[v * 3 + 0], x1 = X[v * 3 + 1], x2 = X[v * 3 + 2];
    float4 w0 = *(const float4*)&Ws[0 * 64 + c4];
    float4 w1 = *(const float4*)&Ws[1 * 64 + c4];
    float4 w2 = *(const float4*)&Ws[2 * 64 + c4];
    float4 o;
    o.x = x0 * w0.x + x1 * w1.x + x2 * w2.x;
    o.y = x0 * w0.y + x1 * w1.y + x2 * w2.y;
    o.z = x0 * w0.z + x1 * w1.z + x2 * w2.z;
    o.w = x0 * w0.w + x1 * w1.w + x2 * w2.w;
    *(float4*)&C[v * 64 + c4] = o;
    float dv = g_dinv[v];
    float sw = dv * dv;
    float4 b4 = *(const float4*)&bias[c4];
    float4 s;
    s.x = b4.x + o.x * sw; s.y = b4.y + o.y * sw;
    s.z = b4.z + o.z * sw; s.w = b4.w + o.w * sw;
    *(float4*)&O[(size_t)v * 64 + c4] = s;
}

// ---------------- 64x64 tiled GEMM + optional fused self-init ---------------
__global__ __launch_bounds__(256) void gemm64_kernel(
    const float* __restrict__ A, const float* __restrict__ W,
    float* __restrict__ C, const float* __restrict__ bias_self,
    float* __restrict__ O, int n, int relu_in)
{
    __shared__ float As[64 * 68];
    __shared__ float Ws[64 * 64];
    int tid = threadIdx.x;
    int rowbase = blockIdx.x * 64;

    for (int i = tid; i < 1024; i += 256)
        ((float4*)Ws)[i] = ((const float4*)W)[i];

    for (int i = tid; i < 1024; i += 256) {
        int r = i >> 4;
        int c4 = (i & 15) * 4;
        float4 v;
        if (rowbase + r < n) v = *(const float4*)&A[(size_t)(rowbase + r) * 64 + c4];
        else v = make_float4(0.f, 0.f, 0.f, 0.f);
        if (relu_in) {
            v.x = fmaxf(v.x, 0.f); v.y = fmaxf(v.y, 0.f);
            v.z = fmaxf(v.z, 0.f); v.w = fmaxf(v.w, 0.f);
        }
        *(float4*)&As[r * 68 + c4] = v;
    }
    __syncthreads();

    int rg = (tid >> 4) * 4;
    int cg = (tid & 15) * 4;
    float4 acc0 = make_float4(0, 0, 0, 0), acc1 = acc0, acc2 = acc0, acc3 = acc0;
#pragma unroll
    for (int k = 0; k < 64; k++) {
        float4 wv = *(const float4*)&Ws[k * 64 + cg];
        float a0 = As[(rg + 0) * 68 + k];
        float a1 = As[(rg + 1) * 68 + k];
        float a2 = As[(rg + 2) * 68 + k];
        float a3 = As[(rg + 3) * 68 + k];
        acc0.x += a0 * wv.x; acc0.y += a0 * wv.y; acc0.z += a0 * wv.z; acc0.w += a0 * wv.w;
        acc1.x += a1 * wv.x; acc1.y += a1 * wv.y; acc1.z += a1 * wv.z; acc1.w += a1 * wv.w;
        acc2.x += a2 * wv.x; acc2.y += a2 * wv.y; acc2.z += a2 * wv.z; acc2.w += a2 * wv.w;
        acc3.x += a3 * wv.x; acc3.y += a3 * wv.y; acc3.z += a3 * wv.z; acc3.w += a3 * wv.w;
    }
    float4 accs[4] = {acc0, acc1, acc2, acc3};
#pragma unroll
    for (int rr = 0; rr < 4; rr++) {
        int row = rowbase + rg + rr;
        if (row < n) {
            *(float4*)&C[(size_t)row * 64 + cg] = accs[rr];
            if (O) {
                float dv = g_dinv[row];
                float sw = dv * dv;
                float4 b4 = *(const float4*)&bias_self[cg];
                float4 s;
                s.x = b4.x + accs[rr].x * sw; s.y = b4.y + accs[rr].y * sw;
                s.z = b4.z + accs[rr].z * sw; s.w = b4.w + accs[rr].w * sw;
                *(float4*)&O[(size_t)row * 64 + cg] = s;
            }
        }
    }
}

// ---------------- edge scatter: O[col] += T[row] * dinv[row]*dinv[col] -------
__global__ __launch_bounds__(256) void scatter_kernel(
    const int* __restrict__ ei, const float* __restrict__ T,
    float* __restrict__ O, int E)
{
    long long idx = (long long)blockIdx.x * 256 + threadIdx.x;
    int e = (int)(idx >> 4);
    int part = ((int)idx & 15) * 4;
    if (e >= E) return;
    int r = ei[e];
    int c = ei[(size_t)E + e];
    float w = g_dinv[r] * g_dinv[c];
    float4 v = *(const float4*)&T[(size_t)r * 64 + part];
    v.x *= w; v.y *= w; v.z *= w; v.w *= w;
    float* p = &O[(size_t)c * 64 + part];
    asm volatile("red.global.add.v4.f32 [%0], {%1,%2,%3,%4};"
                 :: "l"(p), "f"(v.x), "f"(v.y), "f"(v.z), "f"(v.w) : "memory");
}

// ---------------- edge pass 1: BN1 statistics of z1 -------------------------
__global__ __launch_bounds__(256) void edge_pass1_kernel(
    const int* __restrict__ ei, const float* __restrict__ A,
    const float* __restrict__ B, const float* __restrict__ bm1, int E)
{
    int lane = threadIdx.x & 31;
    int wid = threadIdx.x >> 5;
    int gw = blockIdx.x * 8 + wid;
    int nw = gridDim.x * 8;
    float ba = bm1[lane], bb = bm1[lane + 32];
    float s0 = 0.f, q0 = 0.f, s1 = 0.f, q1 = 0.f;
    for (int e = gw; e < E; e += nw) {
        int s = ei[e];
        int d = ei[(size_t)E + e];
        float z = A[(size_t)s * 64 + lane] + B[(size_t)d * 64 + lane] + ba;
        z = fmaxf(z, 0.f);
        float w = A[(size_t)s * 64 + lane + 32] + B[(size_t)d * 64 + lane + 32] + bb;
        w = fmaxf(w, 0.f);
        s0 += z; q0 += z * z;
        s1 += w; q1 += w * w;
    }
    __shared__ float sh[8][64];
    sh[wid][lane] = s0; sh[wid][lane + 32] = s1;
    __syncthreads();
    if (threadIdx.x < 64) {
        float t = 0.f;
        for (int w = 0; w < 8; w++) t += sh[w][threadIdx.x];
        atomicAdd(&g_s1[threadIdx.x], (double)t);
    }
    __syncthreads();
    sh[wid][lane] = q0; sh[wid][lane + 32] = q1;
    __syncthreads();
    if (threadIdx.x < 64) {
        float t = 0.f;
        for (int w = 0; w < 8; w++) t += sh[w][threadIdx.x];
        atomicAdd(&g_q1[threadIdx.x], (double)t);
    }
}

// ---------------- fold BN1 into Wm2 -----------------------------------------
__global__ void fold1_kernel(const float* __restrict__ Wm2,
                             const float* __restrict__ bm2,
                             const float* __restrict__ g1,
                             const float* __restrict__ be1, double inv)
{
    int m = threadIdx.x;  // 32
    float bacc = bm2[m];
    for (int j = 0; j < 64; j++) {
        double mu = g_s1[j] * inv;
        double var = g_q1[j] * inv - mu * mu;
        float s = g1[j] * rsqrtf((float)var + 1e-5f);
        float t = be1[j] - (float)mu * s;
        float w = Wm2[j * 32 + m];
        g_W2f[j * 32 + m] = s * w;
        bacc += t * w;
    }
    g_b2f[m] = bacc;
}

// ---- edge pass 2 (tiled): z2 = relu(z1 @ W2f + b2f); fused BN2 stats -------
__global__ __launch_bounds__(256) void edge_pass2_kernel(
    const int* __restrict__ ei, const float* __restrict__ A,
    const float* __restrict__ B, const float* __restrict__ bm1, int E)
{
    __shared__ float Zs[64][68];     // z1 tile (pad 68 -> 272B rows, 16B aligned)
    __shared__ float Ws[64 * 32];
    __shared__ float bs[64];
    __shared__ float b2s[32];
    __shared__ float blk_s[32], blk_q[32];
    __shared__ int   se[64], de[64];

    int tid = threadIdx.x;
    int lane = tid & 31;
    int wid = tid >> 5;
    if (tid < 64) bs[tid] = bm1[tid];
    if (tid < 32) { b2s[tid] = g_b2f[tid]; blk_s[tid] = 0.f; blk_q[tid] = 0.f; }
    for (int i = tid; i < 2048; i += 256) Ws[i] = g_W2f[i];
    __syncthreads();

    int r0 = (tid >> 3) * 2;        // rows r0, r0+1
    int cg = (tid & 7) * 4;         // cols cg..cg+3

    float st_s[4] = {0.f, 0.f, 0.f, 0.f};
    float st_q[4] = {0.f, 0.f, 0.f, 0.f};

    int ntiles = (E + 63) >> 6;
    for (int tile = blockIdx.x; tile < ntiles; tile += gridDim.x) {
        int e0 = tile << 6;
        int ecount = min(64, E - e0);
        if (tid < ecount) {
            se[tid] = ei[e0 + tid];
            de[tid] = ei[(size_t)E + e0 + tid];
        }
        __syncthreads();

        // stage z1: warp w -> rows w*8 .. w*8+7, coalesced float2 per lane
        int rbase = wid * 8;
#pragma unroll
        for (int rr = 0; rr < 8; rr++) {
            int r = rbase + rr;
            float z0 = 0.f, z1 = 0.f;
            if (r < ecount) {
                int s = se[r], d = de[r];
                float2 a = ((const float2*)&A[(size_t)s * 64])[lane];
                float2 b = ((const float2*)&B[(size_t)d * 64])[lane];
                z0 = fmaxf(a.x + b.x + bs[2 * lane], 0.f);
                z1 = fmaxf(a.y + b.y + bs[2 * lane + 1], 0.f);
            }
            Zs[r][2 * lane] = z0;
            Zs[r][2 * lane + 1] = z1;
        }
        __syncthreads();

        // GEMM: 2 rows x 4 cols per thread over k=64
        float acc0[4], acc1[4];
#pragma unroll
        for (int j = 0; j < 4; j++) { acc0[j] = b2s[cg + j]; acc1[j] = b2s[cg + j]; }
#pragma unroll
        for (int k = 0; k < 64; k += 4) {
            float a0r[4], a1r[4];
            *(float4*)a0r = *(const float4*)&Zs[r0][k];
            *(float4*)a1r = *(const float4*)&Zs[r0 + 1][k];
#pragma unroll
            for (int kk = 0; kk < 4; kk++) {
                float wr[4];
                *(float4*)wr = *(const float4*)&Ws[(k + kk) * 32 + cg];
#pragma unroll
                for (int j = 0; j < 4; j++) {
                    acc0[j] += a0r[kk] * wr[j];
                    acc1[j] += a1r[kk] * wr[j];
                }
            }
        }

        bool v0 = (e0 + r0) < E;
        bool v1 = (e0 + r0 + 1) < E;
        float o0[4], o1[4];
#pragma unroll
        for (int j = 0; j < 4; j++) {
            o0[j] = fmaxf(acc0[j], 0.f);
            o1[j] = fmaxf(acc1[j], 0.f);
        }
        if (v0) {
            *(float4*)&g_z2[(size_t)(e0 + r0) * 32 + cg] = *(float4*)o0;
#pragma unroll
            for (int j = 0; j < 4; j++) { st_s[j] += o0[j]; st_q[j] += o0[j] * o0[j]; }
        }
        if (v1) {
            *(float4*)&g_z2[(size_t)(e0 + r0 + 1) * 32 + cg] = *(float4*)o1;
#pragma unroll
            for (int j = 0; j < 4; j++) { st_s[j] += o1[j]; st_q[j] += o1[j] * o1[j]; }
        }
        __syncthreads();   // before next tile overwrites se/de/Zs
    }

    // flush per-block stats
#pragma unroll
    for (int j = 0; j < 4; j++) {
        atomicAdd(&blk_s[cg + j], st_s[j]);
        atomicAdd(&blk_q[cg + j], st_q[j]);
    }
    __syncthreads();
    if (tid < 32) {
        atomicAdd(&g_s2[tid], (double)blk_s[tid]);
        atomicAdd(&g_q2[tid], (double)blk_q[tid]);
    }
}

// ---------------- fold BN2 into Wm3 -----------------------------------------
__global__ void fold2_kernel(const float* __restrict__ Wm3,
                             const float* __restrict__ bm3,
                             const float* __restrict__ g2,
                             const float* __restrict__ be2, double inv)
{
    int k = threadIdx.x;
    if (k >= 2) return;
    float bacc = bm3[k];
    for (int m = 0; m < 32; m++) {
        double mu = g_s2[m] * inv;
        double var = g_q2[m] * inv - mu * mu;
        float s = g2[m] * rsqrtf((float)var + 1e-5f);
        float t = be2[m] - (float)mu * s;
        float w = Wm3[m * 2 + k];
        g_W3f[m * 2 + k] = s * w;
        bacc += t * w;
    }
    g_b3f[k] = bacc;
}

// ---------------- edge pass 3: out = z2 @ W3f + b3f -------------------------
__global__ __launch_bounds__(256) void edge_pass3_kernel(float* __restrict__ out, int E) {
    __shared__ float W0[32], W1s[32];
    __shared__ float bb[2];
    int tid = threadIdx.x;
    if (tid < 32) { W0[tid] = g_W3f[tid * 2]; W1s[tid] = g_W3f[tid * 2 + 1]; }
    if (tid < 2) bb[tid] = g_b3f[tid];
    __syncthreads();
    int stride = gridDim.x * 256;
    for (int e = blockIdx.x * 256 + tid; e < E; e += stride) {
        const float4* z4 = (const float4*)&g_z2[(size_t)e * 32];
        float o0 = bb[0], o1 = bb[1];
#pragma unroll
        for (int m4 = 0; m4 < 8; m4++) {
            float4 z = z4[m4];
            o0 += z.x * W0[m4 * 4 + 0] + z.y * W0[m4 * 4 + 1] +
                  z.z * W0[m4 * 4 + 2] + z.w * W0[m4 * 4 + 3];
            o1 += z.x * W1s[m4 * 4 + 0] + z.y * W1s[m4 * 4 + 1] +
                  z.z * W1s[m4 * 4 + 2] + z.w * W1s[m4 * 4 + 3];
        }
        *(float2*)&out[(size_t)e * 2] = make_float2(o0, o1);
    }
}

// ---------------- host launcher ---------------------------------------------
extern "C" void kernel_launch(void* const* d_in, const int* in_sizes, int n_in,
                              void* d_out, int out_size)
{
    const float* x = (const float*)d_in[0];
    const int* ei = (const int*)d_in[1];
    const float* W1 = (const float*)d_in[2];
    const float* b1 = (const float*)d_in[3];
    const float* W2 = (const float*)d_in[4];
    const float* b2 = (const float*)d_in[5];
    const float* W3 = (const float*)d_in[6];
    const float* b3 = (const float*)d_in[7];
    const float* Wm1 = (const float*)d_in[8];
    const float* bm1 = (const float*)d_in[9];
    const float* g1 = (const float*)d_in[10];
    const float* be1 = (const float*)d_in[11];
    const float* Wm2 = (const float*)d_in[12];
    const float* bm2 = (const float*)d_in[13];
    const float* g2 = (const float*)d_in[14];
    const float* be2 = (const float*)d_in[15];
    const float* Wm3 = (const float*)d_in[16];
    const float* bm3 = (const float*)d_in[17];

    int n = in_sizes[0] / 3;
    int E = in_sizes[1] / 2;

    float *B0, *B1p, *B2;
    cudaGetSymbolAddress((void**)&B0, g_B0);
    cudaGetSymbolAddress((void**)&B1p, g_B1);
    cudaGetSymbolAddress((void**)&B2, g_B2);

    int nb_node = (n + 255) / 256;
    int nb_edge = (E + 255) / 256;
    int nb_node16 = (n * 16 + 255) / 256;
    int nb_edge16 = (int)(((long long)E * 16 + 255) / 256);
    int nb_gemm = (n + 63) / 64;

    // degree (+ stats zero fused)
    deg_init_kernel<<<nb_node, 256>>>(n);
    deg_count_kernel<<<nb_edge, 256>>>(ei, E);
    deg_finish_kernel<<<nb_node, 256>>>(n);

    // layer 1: B0 = x@W1 ; B1 = b1 + B0*dinv^2 (fused) ; scatter into B1
    gemm_k3_kernel<<<nb_node16, 256>>>(x, W1, b1, B0, B1p, n);
    scatter_kernel<<<nb_edge16, 256>>>(ei, B0, B1p, E);

    // layer 2: B0 = relu(B1)@W2 ; B2 = b2 + B0*dinv^2 (fused) ; scatter into B2
    gemm64_kernel<<<nb_gemm, 256>>>(B1p, W2, B0, b2, B2, n, 1);
    scatter_kernel<<<nb_edge16, 256>>>(ei, B0, B2, E);

    // layer 3: B0 = relu(B2)@W3 ; B1 = b3 + B0*dinv^2 (fused) ; scatter into B1 (= h3)
    gemm64_kernel<<<nb_gemm, 256>>>(B2, W3, B0, b3, B1p, n, 1);
    scatter_kernel<<<nb_edge16, 256>>>(ei, B0, B1p, E);

    // projections: a = h3@Wm1_top -> B0 ; b = h3@Wm1_bot -> B2
    gemm64_kernel<<<nb_gemm, 256>>>(B1p, Wm1, B0, (const float*)0, (float*)0, n, 0);
    gemm64_kernel<<<nb_gemm, 256>>>(B1p, Wm1 + 64 * 64, B2, (const float*)0, (float*)0, n, 0);

    // edge MLP (stats2 fused into pass2)
    edge_pass1_kernel<<<1024, 256>>>(ei, B0, B2, bm1, E);
    fold1_kernel<<<1, 32>>>(Wm2, bm2, g1, be1, 1.0 / (double)E);
    edge_pass2_kernel<<<2048, 256>>>(ei, B0, B2, bm1, E);
    fold2_kernel<<<1, 32>>>(Wm3, bm3, g2, be2, 1.0 / (double)E);
    edge_pass3_kernel<<<2048, 256>>>((float*)d_out, E);
}